// round 14
// baseline (speedup 1.0000x reference)
#include <cuda_runtime.h>
#include <cuda_fp16.h>
#include <cstdint>

// ---------------- problem constants ----------------
#define SIGMA_INV (1.0f / 0.7f)
#define BN_EPS  1e-5f
#define MAXN    50176

// ---------------- scratch ----------------
__device__ float  g_h[MAXN * 64];
__device__ float  g_part[512 * 128];
__device__ float  g_scale[64];
__device__ float  g_shift[64];
__device__ __half g_feats16[MAXN * 64];
__device__ __half g_w2t[960 * 64];
__device__ __half g_cw[(size_t)MAXN * 960];
__device__ uint2  g_meta[MAXN * 32];

// ---------------- f32x2 helpers ----------------
__device__ __forceinline__ unsigned long long pack2(float x, float y) {
    unsigned long long r;
    asm("mov.b64 %0, {%1, %2};" : "=l"(r) : "f"(x), "f"(y));
    return r;
}
__device__ __forceinline__ void unpack2(unsigned long long v, float& x, float& y) {
    asm("mov.b64 {%0, %1}, %2;" : "=f"(x), "=f"(y) : "l"(v));
}
__device__ __forceinline__ void fma2(unsigned long long& acc,
                                     unsigned long long a, unsigned long long b) {
    asm("fma.rn.f32x2 %0, %1, %2, %0;" : "+l"(acc) : "l"(a), "l"(b));
}
__device__ __forceinline__ void add2(unsigned long long& acc, unsigned long long a) {
    asm("add.rn.f32x2 %0, %0, %1;" : "+l"(acc) : "l"(a));
}

// ---------------- HMMA m16n8k16 fp16->fp32 ----------------
__device__ __forceinline__ void mma16816(float* c, const uint32_t* a,
                                         uint32_t b0, uint32_t b1) {
    asm volatile(
        "mma.sync.aligned.m16n8k16.row.col.f32.f16.f16.f32 "
        "{%0,%1,%2,%3}, {%4,%5,%6,%7}, {%8,%9}, {%0,%1,%2,%3};"
        : "+f"(c[0]), "+f"(c[1]), "+f"(c[2]), "+f"(c[3])
        : "r"(a[0]), "r"(a[1]), "r"(a[2]), "r"(a[3]), "r"(b0), "r"(b1));
}

// ================= K1: h = s_feats @ W1 + BN partials + fp16 feats mirror =====
#define K1_SMEM_FLOATS (64 * 130 + 256)
#define K1_SMEM_BYTES  (K1_SMEM_FLOATS * 4)

__global__ void __launch_bounds__(256) k1_feat_mm(
    const float* __restrict__ s_feats, const float* __restrict__ W1, int N)
{
    extern __shared__ float sm1[];
    float* feat_t = sm1;
    float* red    = feat_t + 64 * 130;

    const int tid  = threadIdx.x;
    const int row0 = blockIdx.x * 128;

    #pragma unroll
    for (int it = 0; it < 8; it++) {
        int idx = it * 256 + tid;
        int r   = idx >> 4;
        int c0  = (idx & 15) * 4;
        float4 v = make_float4(0.f, 0.f, 0.f, 0.f);
        if (row0 + r < N) {
            v = *reinterpret_cast<const float4*>(s_feats + (row0 + r) * 64 + c0);
            __half2 h01 = __floats2half2_rn(v.x, v.y);
            __half2 h23 = __floats2half2_rn(v.z, v.w);
            uint2 hp;
            hp.x = *reinterpret_cast<uint32_t*>(&h01);
            hp.y = *reinterpret_cast<uint32_t*>(&h23);
            *reinterpret_cast<uint2*>(g_feats16 + (row0 + r) * 64 + c0) = hp;
        }
        feat_t[(c0 + 0) * 130 + r] = v.x;
        feat_t[(c0 + 1) * 130 + r] = v.y;
        feat_t[(c0 + 2) * 130 + r] = v.z;
        feat_t[(c0 + 3) * 130 + r] = v.w;
    }
    __syncthreads();

    const int cg = tid & 31, rg = tid >> 5;
    const int c0 = cg * 2;
    unsigned long long acc[2][8];
    #pragma unroll
    for (int cc = 0; cc < 2; cc++)
        #pragma unroll
        for (int p = 0; p < 8; p++) acc[cc][p] = 0ull;

    #pragma unroll 4
    for (int cp = 0; cp < 64; cp++) {
        unsigned long long wp = __ldg(
            reinterpret_cast<const unsigned long long*>(W1 + cp * 64 + c0));
        float w0, w1;
        unpack2(wp, w0, w1);
        unsigned long long w00 = pack2(w0, w0), w11 = pack2(w1, w1);
        const unsigned long long* ar =
            reinterpret_cast<const unsigned long long*>(feat_t + cp * 130 + rg * 16);
        #pragma unroll
        for (int p = 0; p < 8; p++) {
            unsigned long long a2 = ar[p];
            fma2(acc[0][p], a2, w00);
            fma2(acc[1][p], a2, w11);
        }
    }

    float sv[2], qv[2];
    #pragma unroll
    for (int cc = 0; cc < 2; cc++) {
        unsigned long long s2 = 0ull, q2 = 0ull;
        #pragma unroll
        for (int p = 0; p < 8; p++) {
            float x0, x1;
            unpack2(acc[cc][p], x0, x1);
            int r = row0 + rg * 16 + 2 * p;
            if (r < N)     g_h[r * 64 + c0 + cc] = x0;
            if (r + 1 < N) g_h[(r + 1) * 64 + c0 + cc] = x1;
            add2(s2, acc[cc][p]);
            fma2(q2, acc[cc][p], acc[cc][p]);
        }
        float ax, ay;
        unpack2(s2, ax, ay); sv[cc] = ax + ay;
        unpack2(q2, ax, ay); qv[cc] = ax + ay;
    }

    #pragma unroll
    for (int pass = 0; pass < 4; pass++) {
        float val = (pass < 2) ? sv[pass] : qv[pass - 2];
        __syncthreads();
        red[tid] = val;
        __syncthreads();
        if (tid < 32) {
            float t = 0.f;
            #pragma unroll
            for (int g = 0; g < 8; g++) t += red[g * 32 + tid];
            int c = tid * 2 + (pass & 1);
            g_part[blockIdx.x * 128 + ((pass < 2) ? 0 : 64) + c] = t;
        }
    }
}

// ================= K2a: BN finalize (1 block, depends on k1) ==================
__global__ void __launch_bounds__(256) k2a_bn(
    const float* __restrict__ gamma, const float* __restrict__ beta, int N, int nb)
{
    __shared__ float red[256];
    const int tid  = threadIdx.x;
    const int c    = tid & 63;
    const int part = tid >> 6;
    float s = 0.f, q = 0.f;
    for (int b = part; b < nb; b += 4) {
        s += g_part[b * 128 + c];
        q += g_part[b * 128 + 64 + c];
    }
    red[tid] = s;
    __syncthreads();
    float sum = 0.f;
    if (tid < 64) sum = red[tid] + red[tid + 64] + red[tid + 128] + red[tid + 192];
    __syncthreads();
    red[tid] = q;
    __syncthreads();
    if (tid < 64) {
        float sq  = red[tid] + red[tid + 64] + red[tid + 128] + red[tid + 192];
        float inv = 1.f / (float)N;
        float mu  = sum * inv;
        float var = sq * inv - mu * mu;
        float sc  = gamma[tid] * rsqrtf(var + BN_EPS);
        g_scale[tid] = sc;
        g_shift[tid] = beta[tid] - mu * sc;
    }
}

// ====== K2b: W2 transpose (blks 0..59) + meta (blks 60+); independent of k1 ===
__global__ void __launch_bounds__(256) k2b_tr_meta(
    const float* __restrict__ W2,
    const float* __restrict__ q_pts, const float* __restrict__ s_pts,
    const int* __restrict__ neighb_inds, const float* __restrict__ kernel_points,
    int N)
{
    const int tid = threadIdx.x;

    if (blockIdx.x < 60) {
        int o0 = blockIdx.x * 1024 + tid * 4;
        #pragma unroll
        for (int e = 0; e < 4; e++) {
            int o = o0 + e;                 // < 61440
            int n = o >> 6, c = o & 63;
            g_w2t[o] = __float2half_rn(W2[c * 960 + n]);
        }
        return;
    }

    int i = (blockIdx.x - 60) * 256 + tid;   // (m,h) flat index
    if (i >= N * 32) return;
    int m = i >> 5;
    int id = neighb_inds[i];
    uint32_t packed = 0u;
    float infl = 0.f;
    if ((unsigned)id < (unsigned)N) {
        float qx = __ldg(q_pts + m * 3 + 0);
        float qy = __ldg(q_pts + m * 3 + 1);
        float qz = __ldg(q_pts + m * 3 + 2);
        float nx = __ldg(s_pts + id * 3 + 0) - qx;
        float ny = __ldg(s_pts + id * 3 + 1) - qy;
        float nz = __ldg(s_pts + id * 3 + 2) - qz;
        float best = 1e30f;
        int kb = 0;
        #pragma unroll
        for (int k = 0; k < 15; k++) {
            float dx = nx - __ldg(kernel_points + k * 3 + 0);
            float dy = ny - __ldg(kernel_points + k * 3 + 1);
            float dz = nz - __ldg(kernel_points + k * 3 + 2);
            float d = fmaf(dx, dx, fmaf(dy, dy, dz * dz));
            if (d < best) { best = d; kb = k; }
        }
        infl = fmaxf(0.f, 1.f - sqrtf(best) * SIGMA_INV);
        packed = (uint32_t)id * 128u + (uint32_t)kb;
    }
    g_meta[i] = make_uint2(packed, __float_as_uint(infl));
}

// ========= K4: persistent-N HMMA GEMM over row range [rs, re) =================
#define AS 72
#define K4_SMEM (18432 + 18432 + 3840)

__global__ void __launch_bounds__(256) k4_gemm(const float* __restrict__ b2,
                                               int N, int rs)
{
    extern __shared__ char sm4[];
    __half* A_s    = (__half*)sm4;
    __half* B_s0   = (__half*)(sm4 + 18432);
    __half* B_s1   = (__half*)(sm4 + 18432 + 9216);
    float*  bias_s = (float*)(sm4 + 18432 + 18432);

    const int tid  = threadIdx.x;
    const int lane = tid & 31, w = tid >> 5;
    const int wm = w & 1, wn = w >> 1;
    const int row0 = rs + blockIdx.x * 128;

    for (int i = tid; i < 960; i += 256) bias_s[i] = b2[i];
    {
        const int c0 = (tid & 15) * 4;
        float4 sc = *reinterpret_cast<const float4*>(g_scale + c0);
        float4 sh = *reinterpret_cast<const float4*>(g_shift + c0);
        #pragma unroll
        for (int it = 0; it < 8; it++) {
            int idx = it * 256 + tid;
            int r = idx >> 4;
            float4 v = make_float4(0.f, 0.f, 0.f, 0.f);
            if (row0 + r < N) {
                float4 h = *reinterpret_cast<const float4*>(g_h + (row0 + r) * 64 + c0);
                v.x = fmaf(h.x, sc.x, sh.x); v.x = (v.x > 0.f) ? v.x : 0.1f * v.x;
                v.y = fmaf(h.y, sc.y, sh.y); v.y = (v.y > 0.f) ? v.y : 0.1f * v.y;
                v.z = fmaf(h.z, sc.z, sh.z); v.z = (v.z > 0.f) ? v.z : 0.1f * v.z;
                v.w = fmaf(h.w, sc.w, sh.w); v.w = (v.w > 0.f) ? v.w : 0.1f * v.w;
            }
            __half2 h01 = __floats2half2_rn(v.x, v.y);
            __half2 h23 = __floats2half2_rn(v.z, v.w);
            uint2 hp;
            hp.x = *reinterpret_cast<uint32_t*>(&h01);
            hp.y = *reinterpret_cast<uint32_t*>(&h23);
            *reinterpret_cast<uint2*>(A_s + r * AS + c0) = hp;
        }
    }

    {
        #pragma unroll
        for (int it = 0; it < 2; it++) {
            int idx = it * 256 + tid;
            int r = idx >> 3, c8 = idx & 7;
            uint32_t dst = (uint32_t)__cvta_generic_to_shared(B_s0 + r * AS + c8 * 8);
            const void* src = g_w2t + r * 64 + c8 * 8;
            asm volatile("cp.async.ca.shared.global [%0], [%1], 16;"
                         :: "r"(dst), "l"(src));
        }
        asm volatile("cp.async.commit_group;");
    }
    __syncthreads();

    const int mrow = lane >> 2;
    const int kcol = (lane & 3) * 2;

    for (int c = 0; c < 15; c++) {
        const int n0 = c * 64;
        __half* Bc = (c & 1) ? B_s1 : B_s0;
        if (c + 1 < 15) {
            __half* Bn = ((c + 1) & 1) ? B_s1 : B_s0;
            #pragma unroll
            for (int it = 0; it < 2; it++) {
                int idx = it * 256 + tid;
                int r = idx >> 3, c8 = idx & 7;
                uint32_t dst = (uint32_t)__cvta_generic_to_shared(Bn + r * AS + c8 * 8);
                const void* src = g_w2t + (n0 + 64 + r) * 64 + c8 * 8;
                asm volatile("cp.async.ca.shared.global [%0], [%1], 16;"
                             :: "r"(dst), "l"(src));
            }
            asm volatile("cp.async.commit_group;");
            asm volatile("cp.async.wait_group 1;");
        } else {
            asm volatile("cp.async.wait_group 0;");
        }
        __syncthreads();

        float acc[4][2][4];
        #pragma unroll
        for (int i = 0; i < 4; i++)
            #pragma unroll
            for (int j = 0; j < 2; j++)
                #pragma unroll
                for (int q = 0; q < 4; q++) acc[i][j][q] = 0.f;

        #pragma unroll
        for (int ks = 0; ks < 4; ks++) {
            const int kb = ks * 16;
            uint32_t a[4][4];
            #pragma unroll
            for (int i = 0; i < 4; i++) {
                const __half* ap = A_s + (wm * 64 + i * 16 + mrow) * AS + kb + kcol;
                a[i][0] = *reinterpret_cast<const uint32_t*>(ap);
                a[i][1] = *reinterpret_cast<const uint32_t*>(ap + 8 * AS);
                a[i][2] = *reinterpret_cast<const uint32_t*>(ap + 8);
                a[i][3] = *reinterpret_cast<const uint32_t*>(ap + 8 * AS + 8);
            }
            #pragma unroll
            for (int j = 0; j < 2; j++) {
                const __half* bp = Bc + (wn * 16 + j * 8 + mrow) * AS + kb + kcol;
                uint32_t b0 = *reinterpret_cast<const uint32_t*>(bp);
                uint32_t b1 = *reinterpret_cast<const uint32_t*>(bp + 8);
                #pragma unroll
                for (int i = 0; i < 4; i++)
                    mma16816(acc[i][j], a[i], b0, b1);
            }
        }

        #pragma unroll
        for (int j = 0; j < 2; j++) {
            int col = n0 + wn * 16 + j * 8 + kcol;
            float bx = bias_s[col], by = bias_s[col + 1];
            #pragma unroll
            for (int i = 0; i < 4; i++) {
                int r = row0 + wm * 64 + i * 16 + mrow;
                if (r < N)
                    *reinterpret_cast<__half2*>(g_cw + (size_t)r * 960 + col) =
                        __floats2half2_rn(acc[i][j][0] + bx, acc[i][j][1] + by);
                if (r + 8 < N)
                    *reinterpret_cast<__half2*>(g_cw + (size_t)(r + 8) * 960 + col) =
                        __floats2half2_rn(acc[i][j][2] + bx, acc[i][j][3] + by);
            }
        }
        __syncthreads();
    }
}

// ================= K5: aggregation over query range [ms, ...) =================
__global__ void __launch_bounds__(512) k5_agg(float* __restrict__ out, int N, int ms)
{
    __shared__ __half cw_s[16 * 960];
    __shared__ uint2  meta_s[512];

    const int tid = threadIdx.x;
    const int m0  = ms + blockIdx.x * 16;

    {
        const uint4* src = reinterpret_cast<const uint4*>(g_cw + (size_t)m0 * 960);
        uint4* dst = reinterpret_cast<uint4*>(cw_s);
        #pragma unroll
        for (int it = 0; it < 4; it++) {
            int i = it * 512 + tid;
            if (i < 1920 && (m0 + i / 120) < N) dst[i] = src[i];
        }
    }
    {
        int i = m0 * 32 + tid;
        if (i < N * 32) meta_s[tid] = g_meta[i];
    }
    __syncthreads();

    const int wid = tid >> 5, lane = tid & 31;
    const int gm = m0 + wid;
    if (gm >= N) return;

    const char* fb  = reinterpret_cast<const char*>(g_feats16) + lane * 4;
    const char* cwb = reinterpret_cast<const char*>(cw_s + wid * 960) + lane * 4;
    const uint2* mp = meta_s + wid * 32;

    float ox = 0.f, oy = 0.f;
    #pragma unroll 8
    for (int h = 0; h < 32; h++) {
        uint2 md = mp[h];
        uint32_t pk = md.x;
        float fl = __uint_as_float(md.y);
        __half2 fh = *reinterpret_cast<const __half2*>(fb + (pk & ~127u));
        __half2 wh = *reinterpret_cast<const __half2*>(cwb + ((pk & 127u) << 7));
        __half2 t  = __hmul2(fh, wh);
        float2 tf  = __half22float2(t);
        ox = fmaf(tf.x, fl, ox);
        oy = fmaf(tf.y, fl, oy);
    }
    *reinterpret_cast<float2*>(out + gm * 64 + 2 * lane) = make_float2(ox, oy);
}

// ================= launch =================
extern "C" void kernel_launch(void* const* d_in, const int* in_sizes, int n_in,
                              void* d_out, int out_size)
{
    const float* q_pts   = (const float*)d_in[0];
    const float* s_pts   = (const float*)d_in[1];
    const float* s_feats = (const float*)d_in[2];
    const int*   neighb  = (const int*)d_in[3];
    const float* kp      = (const float*)d_in[4];
    const float* W1      = (const float*)d_in[5];
    const float* gamma   = (const float*)d_in[6];
    const float* beta    = (const float*)d_in[7];
    const float* W2      = (const float*)d_in[8];
    const float* b2      = (const float*)d_in[9];
    float* out = (float*)d_out;

    const int N      = in_sizes[0] / 3;
    const int nb1    = (N + 127) / 128;
    const int nbMeta = (N * 32 + 255) / 256;
    const int half   = ((N / 2 + 127) / 128) * 128;   // row split, mult of 128
    const int g4a = half / 128;
    const int g4b = (N - half + 127) / 128;
    const int g5a = half / 16;
    const int g5b = (N - half + 15) / 16;

    cudaFuncSetAttribute(k1_feat_mm, cudaFuncAttributeMaxDynamicSharedMemorySize,
                         K1_SMEM_BYTES);
    cudaFuncSetAttribute(k4_gemm, cudaFuncAttributeMaxDynamicSharedMemorySize,
                         K4_SMEM);

    // lazy one-time creation of side stream + events (host-side objects only;
    // created on the eager correctness call, never used outside capture)
    static cudaStream_t s2 = nullptr;
    static cudaEvent_t evFork = nullptr, evSide = nullptr, evH0 = nullptr,
                       evDone = nullptr;
    if (!s2) {
        if (cudaStreamCreateWithFlags(&s2, cudaStreamNonBlocking) != cudaSuccess)
            s2 = nullptr;
        if (s2) {
            cudaEventCreateWithFlags(&evFork, cudaEventDisableTiming);
            cudaEventCreateWithFlags(&evSide, cudaEventDisableTiming);
            cudaEventCreateWithFlags(&evH0,   cudaEventDisableTiming);
            cudaEventCreateWithFlags(&evDone, cudaEventDisableTiming);
        }
    }

    cudaStreamCaptureStatus cst = cudaStreamCaptureStatusNone;
    cudaStreamIsCapturing((cudaStream_t)0, &cst);
    const bool forked = (cst == cudaStreamCaptureStatusActive) && s2;

    if (forked) {
        // fork side stream into the capture
        cudaEventRecord(evFork, (cudaStream_t)0);
        cudaStreamWaitEvent(s2, evFork, 0);

        // side: transpose + meta (independent of k1)
        k2b_tr_meta<<<60 + nbMeta, 256, 0, s2>>>(W2, q_pts, s_pts, neighb, kp, N);
        cudaEventRecord(evSide, s2);

        // main: k1 GEMM + BN finalize
        k1_feat_mm<<<nb1, 256, K1_SMEM_BYTES>>>(s_feats, W1, N);
        k2a_bn<<<1, 256>>>(gamma, beta, N, nb1);

        // main waits for transpose (k4 needs g_w2t)
        cudaStreamWaitEvent((cudaStream_t)0, evSide, 0);

        // k4 half 0 on main
        k4_gemm<<<g4a, 256, K4_SMEM>>>(b2, N, 0);
        cudaEventRecord(evH0, (cudaStream_t)0);

        // side: k5 half 0 (needs k4 h0 + feats16/meta, all ordered via evH0)
        cudaStreamWaitEvent(s2, evH0, 0);
        k5_agg<<<g5a, 512, 0, s2>>>(out, N, 0);
        cudaEventRecord(evDone, s2);

        // main: k4 half 1, then k5 half 1
        k4_gemm<<<g4b, 256, K4_SMEM>>>(b2, N, half);
        k5_agg<<<g5b, 512>>>(out, N, half);

        // join side stream back into main before capture ends
        cudaStreamWaitEvent((cudaStream_t)0, evDone, 0);
    } else {
        // eager (correctness) path: sequential, default stream only
        k2b_tr_meta<<<60 + nbMeta, 256>>>(W2, q_pts, s_pts, neighb, kp, N);
        k1_feat_mm<<<nb1, 256, K1_SMEM_BYTES>>>(s_feats, W1, N);
        k2a_bn<<<1, 256>>>(gamma, beta, N, nb1);
        k4_gemm<<<g4a, 256, K4_SMEM>>>(b2, N, 0);
        k4_gemm<<<g4b, 256, K4_SMEM>>>(b2, N, half);
        k5_agg<<<g5a, 512>>>(out, N, 0);
        k5_agg<<<g5b, 512>>>(out, N, half);
    }
}

// round 15
// speedup vs baseline: 1.0554x; 1.0554x over previous
#include <cuda_runtime.h>
#include <cuda_fp16.h>
#include <cstdint>

// ---------------- problem constants ----------------
#define SIGMA_INV (1.0f / 0.7f)
#define BN_EPS  1e-5f
#define MAXN    50176

// ---------------- scratch ----------------
__device__ float  g_h[MAXN * 64];            // pre-BN activations
__device__ float  g_part[512 * 128];         // BN partials
__device__ float  g_scale[64];
__device__ float  g_shift[64];
__device__ __half g_a16[MAXN * 64];          // fp16 post-activation
__device__ __half g_feats16[MAXN * 64];      // fp16 mirror of s_feats
__device__ __half g_w2t[960 * 64];           // W2^T fp16 [n][k]
__device__ __half g_cw[(size_t)MAXN * 960];  // conv weights fp16
__device__ uint2  g_meta[MAXN * 32];         // {id*128+k, infl bits}

// ---------------- f32x2 helpers ----------------
__device__ __forceinline__ unsigned long long pack2(float x, float y) {
    unsigned long long r;
    asm("mov.b64 %0, {%1, %2};" : "=l"(r) : "f"(x), "f"(y));
    return r;
}
__device__ __forceinline__ void unpack2(unsigned long long v, float& x, float& y) {
    asm("mov.b64 {%0, %1}, %2;" : "=f"(x), "=f"(y) : "l"(v));
}
__device__ __forceinline__ void fma2(unsigned long long& acc,
                                     unsigned long long a, unsigned long long b) {
    asm("fma.rn.f32x2 %0, %1, %2, %0;" : "+l"(acc) : "l"(a), "l"(b));
}
__device__ __forceinline__ void add2(unsigned long long& acc, unsigned long long a) {
    asm("add.rn.f32x2 %0, %0, %1;" : "+l"(acc) : "l"(a));
}

// ---------------- HMMA m16n8k16 fp16->fp32 ----------------
__device__ __forceinline__ void mma16816(float* c, const uint32_t* a,
                                         uint32_t b0, uint32_t b1) {
    asm volatile(
        "mma.sync.aligned.m16n8k16.row.col.f32.f16.f16.f32 "
        "{%0,%1,%2,%3}, {%4,%5,%6,%7}, {%8,%9}, {%0,%1,%2,%3};"
        : "+f"(c[0]), "+f"(c[1]), "+f"(c[2]), "+f"(c[3])
        : "r"(a[0]), "r"(a[1]), "r"(a[2]), "r"(a[3]), "r"(b0), "r"(b1));
}

// ================= K1: h = s_feats @ W1 + BN partials + fp16 feats mirror =====
#define K1_SMEM_FLOATS (64 * 130 + 256)
#define K1_SMEM_BYTES  (K1_SMEM_FLOATS * 4)

__global__ void __launch_bounds__(256) k1_feat_mm(
    const float* __restrict__ s_feats, const float* __restrict__ W1, int N)
{
    extern __shared__ float sm1[];
    float* feat_t = sm1;                 // [k][r] stride 130
    float* red    = feat_t + 64 * 130;   // 256

    const int tid  = threadIdx.x;
    const int row0 = blockIdx.x * 128;

    #pragma unroll
    for (int it = 0; it < 8; it++) {
        int idx = it * 256 + tid;
        int r   = idx >> 4;
        int c0  = (idx & 15) * 4;
        float4 v = make_float4(0.f, 0.f, 0.f, 0.f);
        if (row0 + r < N) {
            v = *reinterpret_cast<const float4*>(s_feats + (row0 + r) * 64 + c0);
            __half2 h01 = __floats2half2_rn(v.x, v.y);
            __half2 h23 = __floats2half2_rn(v.z, v.w);
            uint2 hp;
            hp.x = *reinterpret_cast<uint32_t*>(&h01);
            hp.y = *reinterpret_cast<uint32_t*>(&h23);
            *reinterpret_cast<uint2*>(g_feats16 + (row0 + r) * 64 + c0) = hp;
        }
        feat_t[(c0 + 0) * 130 + r] = v.x;
        feat_t[(c0 + 1) * 130 + r] = v.y;
        feat_t[(c0 + 2) * 130 + r] = v.z;
        feat_t[(c0 + 3) * 130 + r] = v.w;
    }
    __syncthreads();

    const int cg = tid & 31, rg = tid >> 5;
    const int c0 = cg * 2;
    unsigned long long acc[2][8];
    #pragma unroll
    for (int cc = 0; cc < 2; cc++)
        #pragma unroll
        for (int p = 0; p < 8; p++) acc[cc][p] = 0ull;

    #pragma unroll 4
    for (int cp = 0; cp < 64; cp++) {
        unsigned long long wp = __ldg(
            reinterpret_cast<const unsigned long long*>(W1 + cp * 64 + c0));
        float w0, w1;
        unpack2(wp, w0, w1);
        unsigned long long w00 = pack2(w0, w0), w11 = pack2(w1, w1);
        const unsigned long long* ar =
            reinterpret_cast<const unsigned long long*>(feat_t + cp * 130 + rg * 16);
        #pragma unroll
        for (int p = 0; p < 8; p++) {
            unsigned long long a2 = ar[p];
            fma2(acc[0][p], a2, w00);
            fma2(acc[1][p], a2, w11);
        }
    }

    float sv[2], qv[2];
    #pragma unroll
    for (int cc = 0; cc < 2; cc++) {
        unsigned long long s2 = 0ull, q2 = 0ull;
        #pragma unroll
        for (int p = 0; p < 8; p++) {
            float x0, x1;
            unpack2(acc[cc][p], x0, x1);
            int r = row0 + rg * 16 + 2 * p;
            if (r < N)     g_h[r * 64 + c0 + cc] = x0;
            if (r + 1 < N) g_h[(r + 1) * 64 + c0 + cc] = x1;
            add2(s2, acc[cc][p]);
            fma2(q2, acc[cc][p], acc[cc][p]);
        }
        float ax, ay;
        unpack2(s2, ax, ay); sv[cc] = ax + ay;
        unpack2(q2, ax, ay); qv[cc] = ax + ay;
    }

    #pragma unroll
    for (int pass = 0; pass < 4; pass++) {
        float val = (pass < 2) ? sv[pass] : qv[pass - 2];
        __syncthreads();
        red[tid] = val;
        __syncthreads();
        if (tid < 32) {
            float t = 0.f;
            #pragma unroll
            for (int g = 0; g < 8; g++) t += red[g * 32 + tid];
            int c = tid * 2 + (pass & 1);
            g_part[blockIdx.x * 128 + ((pass < 2) ? 0 : 64) + c] = t;
        }
    }
}

// ====== K2: BN finalize (blk 0) + W2 transpose (blks 1..60) + meta (blks 61+) ==
__global__ void __launch_bounds__(256) k2_bn_tr_meta(
    const float* __restrict__ gamma, const float* __restrict__ beta,
    const float* __restrict__ W2,
    const float* __restrict__ q_pts, const float* __restrict__ s_pts,
    const int* __restrict__ neighb_inds, const float* __restrict__ kernel_points,
    int N, int nb)
{
    const int tid = threadIdx.x;

    if (blockIdx.x == 0) {
        __shared__ float red[256];
        const int c    = tid & 63;
        const int part = tid >> 6;
        float s = 0.f, q = 0.f;
        for (int b = part; b < nb; b += 4) {
            s += g_part[b * 128 + c];
            q += g_part[b * 128 + 64 + c];
        }
        red[tid] = s;
        __syncthreads();
        float sum = 0.f;
        if (tid < 64) sum = red[tid] + red[tid + 64] + red[tid + 128] + red[tid + 192];
        __syncthreads();
        red[tid] = q;
        __syncthreads();
        if (tid < 64) {
            float sq  = red[tid] + red[tid + 64] + red[tid + 128] + red[tid + 192];
            float inv = 1.f / (float)N;
            float mu  = sum * inv;
            float var = sq * inv - mu * mu;
            float sc  = gamma[tid] * rsqrtf(var + BN_EPS);
            g_scale[tid] = sc;
            g_shift[tid] = beta[tid] - mu * sc;
        }
        return;
    }

    if (blockIdx.x <= 60) {
        int o0 = (blockIdx.x - 1) * 1024 + tid * 4;
        #pragma unroll
        for (int e = 0; e < 4; e++) {
            int o = o0 + e;                 // < 61440
            int n = o >> 6, c = o & 63;
            g_w2t[o] = __float2half_rn(W2[c * 960 + n]);
        }
        return;
    }

    // ---------- metadata blocks ----------
    int i = (blockIdx.x - 61) * 256 + tid;
    if (i >= N * 32) return;
    int m = i >> 5;
    int id = neighb_inds[i];
    uint32_t packed = 0u;
    float infl = 0.f;
    if ((unsigned)id < (unsigned)N) {
        float qx = __ldg(q_pts + m * 3 + 0);
        float qy = __ldg(q_pts + m * 3 + 1);
        float qz = __ldg(q_pts + m * 3 + 2);
        float nx = __ldg(s_pts + id * 3 + 0) - qx;
        float ny = __ldg(s_pts + id * 3 + 1) - qy;
        float nz = __ldg(s_pts + id * 3 + 2) - qz;
        float best = 1e30f;
        int kb = 0;
        #pragma unroll
        for (int k = 0; k < 15; k++) {
            float dx = nx - __ldg(kernel_points + k * 3 + 0);
            float dy = ny - __ldg(kernel_points + k * 3 + 1);
            float dz = nz - __ldg(kernel_points + k * 3 + 2);
            float d = fmaf(dx, dx, fmaf(dy, dy, dz * dz));
            if (d < best) { best = d; kb = k; }
        }
        infl = fmaxf(0.f, 1.f - sqrtf(best) * SIGMA_INV);
        packed = (uint32_t)id * 128u + (uint32_t)kb;
    }
    g_meta[i] = make_uint2(packed, __float_as_uint(infl));
}

// ================= K3: activation -> fp16 (once) ==============================
__global__ void __launch_bounds__(256) k3_act(int N)
{
    int p = blockIdx.x * 256 + threadIdx.x;     // half2-pair index
    if (p >= N * 32) return;
    int c = (p & 31) * 2;
    float2 h  = *reinterpret_cast<const float2*>(g_h + 2 * p);
    float2 sc = *reinterpret_cast<const float2*>(g_scale + c);
    float2 sh = *reinterpret_cast<const float2*>(g_shift + c);
    float x = fmaf(h.x, sc.x, sh.x); x = (x > 0.f) ? x : 0.1f * x;
    float y = fmaf(h.y, sc.y, sh.y); y = (y > 0.f) ? y : 0.1f * y;
    *reinterpret_cast<__half2*>(g_a16 + 2 * p) = __floats2half2_rn(x, y);
}

// ===== K4: one block = one (128-row m-tile, 64-col n-chunk); grid (391,15) ====
// smem: A_s 128x72 (18432) + B_s 64x72 (9216) + O_s 128x64 (16384) = 44032 B
#define AS 72
#define K4_SMEM (18432 + 9216 + 16384)

__global__ void __launch_bounds__(256) k4_gemm(const float* __restrict__ b2, int N)
{
    extern __shared__ char sm4[];
    __half* A_s = (__half*)sm4;
    __half* B_s = (__half*)(sm4 + 18432);
    __half* O_s = (__half*)(sm4 + 18432 + 9216);

    const int tid  = threadIdx.x;
    const int lane = tid & 31, w = tid >> 5;
    const int wm = w & 1, wn = w >> 1;
    const int row0 = blockIdx.x * 128;
    const int n0   = blockIdx.y * 64;

    // load A tile: 128 rows x 128B fp16, coalesced (8 uint4 per row)
    #pragma unroll
    for (int it = 0; it < 4; it++) {
        int idx = it * 256 + tid;            // 0..1023
        int r = idx >> 3, c8 = idx & 7;
        uint4 v = make_uint4(0u, 0u, 0u, 0u);
        if (row0 + r < N)
            v = *reinterpret_cast<const uint4*>(g_a16 + (row0 + r) * 64 + c8 * 8);
        *reinterpret_cast<uint4*>(A_s + r * AS + c8 * 8) = v;
    }
    // load B tile: 64 rows x 128B
    #pragma unroll
    for (int it = 0; it < 2; it++) {
        int idx = it * 256 + tid;
        int r = idx >> 3, c8 = idx & 7;
        *reinterpret_cast<uint4*>(B_s + r * AS + c8 * 8) =
            *reinterpret_cast<const uint4*>(g_w2t + (n0 + r) * 64 + c8 * 8);
    }
    __syncthreads();

    const int mrow = lane >> 2;
    const int kcol = (lane & 3) * 2;

    float acc[4][2][4];
    #pragma unroll
    for (int i = 0; i < 4; i++)
        #pragma unroll
        for (int j = 0; j < 2; j++)
            #pragma unroll
            for (int q = 0; q < 4; q++) acc[i][j][q] = 0.f;

    #pragma unroll
    for (int ks = 0; ks < 4; ks++) {
        const int kb = ks * 16;
        uint32_t a[4][4];
        #pragma unroll
        for (int i = 0; i < 4; i++) {
            const __half* ap = A_s + (wm * 64 + i * 16 + mrow) * AS + kb + kcol;
            a[i][0] = *reinterpret_cast<const uint32_t*>(ap);
            a[i][1] = *reinterpret_cast<const uint32_t*>(ap + 8 * AS);
            a[i][2] = *reinterpret_cast<const uint32_t*>(ap + 8);
            a[i][3] = *reinterpret_cast<const uint32_t*>(ap + 8 * AS + 8);
        }
        #pragma unroll
        for (int j = 0; j < 2; j++) {
            const __half* bp = B_s + (wn * 16 + j * 8 + mrow) * AS + kb + kcol;
            uint32_t b0 = *reinterpret_cast<const uint32_t*>(bp);
            uint32_t b1 = *reinterpret_cast<const uint32_t*>(bp + 8);
            #pragma unroll
            for (int i = 0; i < 4; i++)
                mma16816(acc[i][j], a[i], b0, b1);
        }
    }

    // epilogue: bias + fp16 into smem tile
    #pragma unroll
    for (int j = 0; j < 2; j++) {
        int colL = wn * 16 + j * 8 + kcol;   // 0..63
        float bx = __ldg(b2 + n0 + colL);
        float by = __ldg(b2 + n0 + colL + 1);
        #pragma unroll
        for (int i = 0; i < 4; i++) {
            int rL = wm * 64 + i * 16 + mrow;
            *reinterpret_cast<__half2*>(O_s + rL * 64 + colL) =
                __floats2half2_rn(acc[i][j][0] + bx, acc[i][j][1] + by);
            *reinterpret_cast<__half2*>(O_s + (rL + 8) * 64 + colL) =
                __floats2half2_rn(acc[i][j][2] + bx, acc[i][j][3] + by);
        }
    }
    __syncthreads();

    // coalesced store: 128 rows x 128B (8 uint4/row)
    #pragma unroll
    for (int it = 0; it < 4; it++) {
        int idx = it * 256 + tid;            // 0..1023
        int r = idx >> 3, c = (idx & 7) * 8;
        if (row0 + r < N)
            *reinterpret_cast<uint4*>(g_cw + (size_t)(row0 + r) * 960 + n0 + c) =
                *reinterpret_cast<const uint4*>(O_s + r * 64 + c);
    }
}

// ================= K5: aggregation (R11/R13 proven version) ===================
__global__ void __launch_bounds__(512) k5_agg(float* __restrict__ out, int N)
{
    __shared__ __half cw_s[16 * 960];
    __shared__ uint2  meta_s[512];

    const int tid = threadIdx.x;
    const int m0  = blockIdx.x * 16;

    {
        const uint4* src = reinterpret_cast<const uint4*>(g_cw + (size_t)m0 * 960);
        uint4* dst = reinterpret_cast<uint4*>(cw_s);
        #pragma unroll
        for (int it = 0; it < 4; it++) {
            int i = it * 512 + tid;
            if (i < 1920 && (m0 + i / 120) < N) dst[i] = src[i];
        }
    }
    {
        int i = m0 * 32 + tid;
        if (i < N * 32) meta_s[tid] = g_meta[i];
    }
    __syncthreads();

    const int wid = tid >> 5, lane = tid & 31;
    const int gm = m0 + wid;
    if (gm >= N) return;

    const char* fb  = reinterpret_cast<const char*>(g_feats16) + lane * 4;
    const char* cwb = reinterpret_cast<const char*>(cw_s + wid * 960) + lane * 4;
    const uint2* mp = meta_s + wid * 32;

    float ox = 0.f, oy = 0.f;
    #pragma unroll 8
    for (int h = 0; h < 32; h++) {
        uint2 md = mp[h];
        uint32_t pk = md.x;
        float fl = __uint_as_float(md.y);
        __half2 fh = *reinterpret_cast<const __half2*>(fb + (pk & ~127u));
        __half2 wh = *reinterpret_cast<const __half2*>(cwb + ((pk & 127u) << 7));
        __half2 t  = __hmul2(fh, wh);
        float2 tf  = __half22float2(t);
        ox = fmaf(tf.x, fl, ox);
        oy = fmaf(tf.y, fl, oy);
    }
    *reinterpret_cast<float2*>(out + gm * 64 + 2 * lane) = make_float2(ox, oy);
}

// ================= launch =================
extern "C" void kernel_launch(void* const* d_in, const int* in_sizes, int n_in,
                              void* d_out, int out_size)
{
    const float* q_pts   = (const float*)d_in[0];
    const float* s_pts   = (const float*)d_in[1];
    const float* s_feats = (const float*)d_in[2];
    const int*   neighb  = (const int*)d_in[3];
    const float* kp      = (const float*)d_in[4];
    const float* W1      = (const float*)d_in[5];
    const float* gamma   = (const float*)d_in[6];
    const float* beta    = (const float*)d_in[7];
    const float* W2      = (const float*)d_in[8];
    const float* b2      = (const float*)d_in[9];
    float* out = (float*)d_out;

    const int N      = in_sizes[0] / 3;
    const int nb1    = (N + 127) / 128;
    const int nbMeta = (N * 32 + 255) / 256;

    cudaFuncSetAttribute(k1_feat_mm, cudaFuncAttributeMaxDynamicSharedMemorySize,
                         K1_SMEM_BYTES);
    cudaFuncSetAttribute(k4_gemm, cudaFuncAttributeMaxDynamicSharedMemorySize,
                         K4_SMEM);

    k1_feat_mm<<<nb1, 256, K1_SMEM_BYTES>>>(s_feats, W1, N);
    k2_bn_tr_meta<<<61 + nbMeta, 256>>>(gamma, beta, W2, q_pts, s_pts,
                                        neighb, kp, N, nb1);
    k3_act<<<(N * 32 + 255) / 256, 256>>>(N);
    dim3 g4(nb1, 15);
    k4_gemm<<<g4, 256, K4_SMEM>>>(b2, N);
    k5_agg<<<(N + 15) / 16, 512>>>(out, N);
}

// round 16
// speedup vs baseline: 1.1160x; 1.0574x over previous
#include <cuda_runtime.h>
#include <cuda_fp16.h>
#include <cstdint>

// ---------------- problem constants ----------------
#define SIGMA_INV (1.0f / 0.7f)
#define BN_EPS  1e-5f
#define MAXN    50176

// ---------------- scratch ----------------
__device__ float  g_h[MAXN * 64];            // pre-BN activations
__device__ float  g_part[512 * 128];         // BN partials
__device__ float  g_scale[64];
__device__ float  g_shift[64];
__device__ __half g_a16[MAXN * 64];          // fp16 post-activation
__device__ __half g_feats16[MAXN * 64];      // fp16 mirror of s_feats
__device__ __half g_w2t[960 * 64];           // W2^T fp16 [n][k]
__device__ __half g_cw[(size_t)MAXN * 960];  // conv weights fp16
__device__ uint2  g_meta[MAXN * 32];         // {id*128+k, infl bits}

// ---------------- f32x2 helpers ----------------
__device__ __forceinline__ unsigned long long pack2(float x, float y) {
    unsigned long long r;
    asm("mov.b64 %0, {%1, %2};" : "=l"(r) : "f"(x), "f"(y));
    return r;
}
__device__ __forceinline__ void unpack2(unsigned long long v, float& x, float& y) {
    asm("mov.b64 {%0, %1}, %2;" : "=f"(x), "=f"(y) : "l"(v));
}
__device__ __forceinline__ void fma2(unsigned long long& acc,
                                     unsigned long long a, unsigned long long b) {
    asm("fma.rn.f32x2 %0, %1, %2, %0;" : "+l"(acc) : "l"(a), "l"(b));
}
__device__ __forceinline__ void add2(unsigned long long& acc, unsigned long long a) {
    asm("add.rn.f32x2 %0, %0, %1;" : "+l"(acc) : "l"(a));
}

// ---------------- HMMA m16n8k16 + ldmatrix ----------------
__device__ __forceinline__ void mma16816(float* c, const uint32_t* a,
                                         uint32_t b0, uint32_t b1) {
    asm volatile(
        "mma.sync.aligned.m16n8k16.row.col.f32.f16.f16.f32 "
        "{%0,%1,%2,%3}, {%4,%5,%6,%7}, {%8,%9}, {%0,%1,%2,%3};"
        : "+f"(c[0]), "+f"(c[1]), "+f"(c[2]), "+f"(c[3])
        : "r"(a[0]), "r"(a[1]), "r"(a[2]), "r"(a[3]), "r"(b0), "r"(b1));
}
__device__ __forceinline__ void ldm_x4(uint32_t& r0, uint32_t& r1,
                                       uint32_t& r2, uint32_t& r3, uint32_t addr) {
    asm volatile("ldmatrix.sync.aligned.m8n8.x4.shared.b16 {%0,%1,%2,%3}, [%4];"
                 : "=r"(r0), "=r"(r1), "=r"(r2), "=r"(r3) : "r"(addr));
}

// ================= K1: h = s_feats @ W1 + BN partials + fp16 feats mirror =====
#define K1_SMEM_FLOATS (64 * 130 + 256)
#define K1_SMEM_BYTES  (K1_SMEM_FLOATS * 4)

__global__ void __launch_bounds__(256) k1_feat_mm(
    const float* __restrict__ s_feats, const float* __restrict__ W1, int N)
{
    extern __shared__ float sm1[];
    float* feat_t = sm1;
    float* red    = feat_t + 64 * 130;

    const int tid  = threadIdx.x;
    const int row0 = blockIdx.x * 128;

    #pragma unroll
    for (int it = 0; it < 8; it++) {
        int idx = it * 256 + tid;
        int r   = idx >> 4;
        int c0  = (idx & 15) * 4;
        float4 v = make_float4(0.f, 0.f, 0.f, 0.f);
        if (row0 + r < N) {
            v = *reinterpret_cast<const float4*>(s_feats + (row0 + r) * 64 + c0);
            __half2 h01 = __floats2half2_rn(v.x, v.y);
            __half2 h23 = __floats2half2_rn(v.z, v.w);
            uint2 hp;
            hp.x = *reinterpret_cast<uint32_t*>(&h01);
            hp.y = *reinterpret_cast<uint32_t*>(&h23);
            *reinterpret_cast<uint2*>(g_feats16 + (row0 + r) * 64 + c0) = hp;
        }
        feat_t[(c0 + 0) * 130 + r] = v.x;
        feat_t[(c0 + 1) * 130 + r] = v.y;
        feat_t[(c0 + 2) * 130 + r] = v.z;
        feat_t[(c0 + 3) * 130 + r] = v.w;
    }
    __syncthreads();

    const int cg = tid & 31, rg = tid >> 5;
    const int c0 = cg * 2;
    unsigned long long acc[2][8];
    #pragma unroll
    for (int cc = 0; cc < 2; cc++)
        #pragma unroll
        for (int p = 0; p < 8; p++) acc[cc][p] = 0ull;

    #pragma unroll 4
    for (int cp = 0; cp < 64; cp++) {
        unsigned long long wp = __ldg(
            reinterpret_cast<const unsigned long long*>(W1 + cp * 64 + c0));
        float w0, w1;
        unpack2(wp, w0, w1);
        unsigned long long w00 = pack2(w0, w0), w11 = pack2(w1, w1);
        const unsigned long long* ar =
            reinterpret_cast<const unsigned long long*>(feat_t + cp * 130 + rg * 16);
        #pragma unroll
        for (int p = 0; p < 8; p++) {
            unsigned long long a2 = ar[p];
            fma2(acc[0][p], a2, w00);
            fma2(acc[1][p], a2, w11);
        }
    }

    float sv[2], qv[2];
    #pragma unroll
    for (int cc = 0; cc < 2; cc++) {
        unsigned long long s2 = 0ull, q2 = 0ull;
        #pragma unroll
        for (int p = 0; p < 8; p++) {
            float x0, x1;
            unpack2(acc[cc][p], x0, x1);
            int r = row0 + rg * 16 + 2 * p;
            if (r < N)     g_h[r * 64 + c0 + cc] = x0;
            if (r + 1 < N) g_h[(r + 1) * 64 + c0 + cc] = x1;
            add2(s2, acc[cc][p]);
            fma2(q2, acc[cc][p], acc[cc][p]);
        }
        float ax, ay;
        unpack2(s2, ax, ay); sv[cc] = ax + ay;
        unpack2(q2, ax, ay); qv[cc] = ax + ay;
    }

    #pragma unroll
    for (int pass = 0; pass < 4; pass++) {
        float val = (pass < 2) ? sv[pass] : qv[pass - 2];
        __syncthreads();
        red[tid] = val;
        __syncthreads();
        if (tid < 32) {
            float t = 0.f;
            #pragma unroll
            for (int g = 0; g < 8; g++) t += red[g * 32 + tid];
            int c = tid * 2 + (pass & 1);
            g_part[blockIdx.x * 128 + ((pass < 2) ? 0 : 64) + c] = t;
        }
    }
}

// ====== K2: BN finalize (blk 0) + W2 transpose (blks 1..60) + meta (blks 61+) ==
__global__ void __launch_bounds__(256) k2_bn_tr_meta(
    const float* __restrict__ gamma, const float* __restrict__ beta,
    const float* __restrict__ W2,
    const float* __restrict__ q_pts, const float* __restrict__ s_pts,
    const int* __restrict__ neighb_inds, const float* __restrict__ kernel_points,
    int N, int nb)
{
    const int tid = threadIdx.x;

    if (blockIdx.x == 0) {
        __shared__ float red[256];
        const int c    = tid & 63;
        const int part = tid >> 6;
        float s = 0.f, q = 0.f;
        for (int b = part; b < nb; b += 4) {
            s += g_part[b * 128 + c];
            q += g_part[b * 128 + 64 + c];
        }
        red[tid] = s;
        __syncthreads();
        float sum = 0.f;
        if (tid < 64) sum = red[tid] + red[tid + 64] + red[tid + 128] + red[tid + 192];
        __syncthreads();
        red[tid] = q;
        __syncthreads();
        if (tid < 64) {
            float sq  = red[tid] + red[tid + 64] + red[tid + 128] + red[tid + 192];
            float inv = 1.f / (float)N;
            float mu  = sum * inv;
            float var = sq * inv - mu * mu;
            float sc  = gamma[tid] * rsqrtf(var + BN_EPS);
            g_scale[tid] = sc;
            g_shift[tid] = beta[tid] - mu * sc;
        }
        return;
    }

    if (blockIdx.x <= 60) {
        int o0 = (blockIdx.x - 1) * 1024 + tid * 4;
        #pragma unroll
        for (int e = 0; e < 4; e++) {
            int o = o0 + e;                 // < 61440
            int n = o >> 6, c = o & 63;
            g_w2t[o] = __float2half_rn(W2[c * 960 + n]);
        }
        return;
    }

    // ---------- metadata blocks ----------
    int i = (blockIdx.x - 61) * 256 + tid;
    if (i >= N * 32) return;
    int m = i >> 5;
    int id = neighb_inds[i];
    uint32_t packed = 0u;
    float infl = 0.f;
    if ((unsigned)id < (unsigned)N) {
        float qx = __ldg(q_pts + m * 3 + 0);
        float qy = __ldg(q_pts + m * 3 + 1);
        float qz = __ldg(q_pts + m * 3 + 2);
        float nx = __ldg(s_pts + id * 3 + 0) - qx;
        float ny = __ldg(s_pts + id * 3 + 1) - qy;
        float nz = __ldg(s_pts + id * 3 + 2) - qz;
        float best = 1e30f;
        int kb = 0;
        #pragma unroll
        for (int k = 0; k < 15; k++) {
            float dx = nx - __ldg(kernel_points + k * 3 + 0);
            float dy = ny - __ldg(kernel_points + k * 3 + 1);
            float dz = nz - __ldg(kernel_points + k * 3 + 2);
            float d = fmaf(dx, dx, fmaf(dy, dy, dz * dz));
            if (d < best) { best = d; kb = k; }
        }
        infl = fmaxf(0.f, 1.f - sqrtf(best) * SIGMA_INV);
        packed = (uint32_t)id * 128u + (uint32_t)kb;
    }
    g_meta[i] = make_uint2(packed, __float_as_uint(infl));
}

// ================= K3: activation -> fp16 (once) ==============================
__global__ void __launch_bounds__(256) k3_act(int N)
{
    int p = blockIdx.x * 256 + threadIdx.x;
    if (p >= N * 32) return;
    int c = (p & 31) * 2;
    float2 h  = *reinterpret_cast<const float2*>(g_h + 2 * p);
    float2 sc = *reinterpret_cast<const float2*>(g_scale + c);
    float2 sh = *reinterpret_cast<const float2*>(g_shift + c);
    float x = fmaf(h.x, sc.x, sh.x); x = (x > 0.f) ? x : 0.1f * x;
    float y = fmaf(h.y, sc.y, sh.y); y = (y > 0.f) ? y : 0.1f * y;
    *reinterpret_cast<__half2*>(g_a16 + 2 * p) = __floats2half2_rn(x, y);
}

// ===== K4: one block = one (128-row m-tile, 64-col n-chunk); ldmatrix loads ===
// smem: A_s 128x72 (18432) + B_s 64x72 (9216) = 27648 B
#define AS 72
#define K4_SMEM (18432 + 9216)

__global__ void __launch_bounds__(256) k4_gemm(const float* __restrict__ b2, int N)
{
    extern __shared__ char sm4[];
    __half* A_s = (__half*)sm4;
    __half* B_s = (__half*)(sm4 + 18432);

    const int tid  = threadIdx.x;
    const int lane = tid & 31, w = tid >> 5;
    const int wm = w & 1, wn = w >> 1;
    const int row0 = blockIdx.x * 128;
    const int n0   = blockIdx.y * 64;

    // load A tile: 128 rows x 128B fp16 (8 uint4 per row)
    #pragma unroll
    for (int it = 0; it < 4; it++) {
        int idx = it * 256 + tid;
        int r = idx >> 3, c8 = idx & 7;
        uint4 v = make_uint4(0u, 0u, 0u, 0u);
        if (row0 + r < N)
            v = *reinterpret_cast<const uint4*>(g_a16 + (row0 + r) * 64 + c8 * 8);
        *reinterpret_cast<uint4*>(A_s + r * AS + c8 * 8) = v;
    }
    // load B tile: 64 rows x 128B
    #pragma unroll
    for (int it = 0; it < 2; it++) {
        int idx = it * 256 + tid;
        int r = idx >> 3, c8 = idx & 7;
        *reinterpret_cast<uint4*>(B_s + r * AS + c8 * 8) =
            *reinterpret_cast<const uint4*>(g_w2t + (n0 + r) * 64 + c8 * 8);
    }
    __syncthreads();

    // ldmatrix lane address components
    const int lr  = lane & 7;             // row within 8x8 tile
    const int g1  = (lane >> 3) & 1;      // tile pair selector
    const int g2  = lane >> 4;            // tile pair selector (hi)

    // A: lanes[0-7]=m+lr/k0, [8-15]=m+8+lr/k0, [16-23]=m+lr/k8, [24-31]=m+8+lr/k8
    // per-i base (kb=0): row = wm*64 + i*16 + g1*8 + lr, col = g2*8
    uint32_t a_base[4];
    #pragma unroll
    for (int i = 0; i < 4; i++) {
        int rowA = wm * 64 + i * 16 + g1 * 8 + lr;
        a_base[i] = (uint32_t)__cvta_generic_to_shared(A_s + rowA * AS + g2 * 8);
    }
    // B: lanes[0-7]=n+lr/k0, [8-15]=n+lr/k8, [16-23]=n+8+lr/k0, [24-31]=n+8+lr/k8
    int rowB = wn * 16 + g2 * 8 + lr;
    uint32_t b_base = (uint32_t)__cvta_generic_to_shared(B_s + rowB * AS + g1 * 8);

    float acc[4][2][4];
    #pragma unroll
    for (int i = 0; i < 4; i++)
        #pragma unroll
        for (int j = 0; j < 2; j++)
            #pragma unroll
            for (int q = 0; q < 4; q++) acc[i][j][q] = 0.f;

    #pragma unroll
    for (int ks = 0; ks < 4; ks++) {
        const uint32_t koff = ks * 32;     // 16 halfs = 32 bytes
        uint32_t b0j0, b1j0, b0j1, b1j1;
        ldm_x4(b0j0, b1j0, b0j1, b1j1, b_base + koff);
        #pragma unroll
        for (int i = 0; i < 4; i++) {
            uint32_t a[4];
            ldm_x4(a[0], a[1], a[2], a[3], a_base[i] + koff);
            mma16816(acc[i][0], a, b0j0, b1j0);
            mma16816(acc[i][1], a, b0j1, b1j1);
        }
    }

    // epilogue: bias + fp16 direct store
    const int mrow = lane >> 2;
    const int kcol = (lane & 3) * 2;
    #pragma unroll
    for (int j = 0; j < 2; j++) {
        int col = n0 + wn * 16 + j * 8 + kcol;
        float bx = __ldg(b2 + col);
        float by = __ldg(b2 + col + 1);
        #pragma unroll
        for (int i = 0; i < 4; i++) {
            int r = row0 + wm * 64 + i * 16 + mrow;
            if (r < N)
                *reinterpret_cast<__half2*>(g_cw + (size_t)r * 960 + col) =
                    __floats2half2_rn(acc[i][j][0] + bx, acc[i][j][1] + by);
            if (r + 8 < N)
                *reinterpret_cast<__half2*>(g_cw + (size_t)(r + 8) * 960 + col) =
                    __floats2half2_rn(acc[i][j][2] + bx, acc[i][j][3] + by);
        }
    }
}

// ================= K5: aggregation (proven R11 version) =======================
__global__ void __launch_bounds__(512) k5_agg(float* __restrict__ out, int N)
{
    __shared__ __half cw_s[16 * 960];
    __shared__ uint2  meta_s[512];

    const int tid = threadIdx.x;
    const int m0  = blockIdx.x * 16;

    {
        const uint4* src = reinterpret_cast<const uint4*>(g_cw + (size_t)m0 * 960);
        uint4* dst = reinterpret_cast<uint4*>(cw_s);
        #pragma unroll
        for (int it = 0; it < 4; it++) {
            int i = it * 512 + tid;
            if (i < 1920 && (m0 + i / 120) < N) dst[i] = src[i];
        }
    }
    {
        int i = m0 * 32 + tid;
        if (i < N * 32) meta_s[tid] = g_meta[i];
    }
    __syncthreads();

    const int wid = tid >> 5, lane = tid & 31;
    const int gm = m0 + wid;
    if (gm >= N) return;

    const char* fb  = reinterpret_cast<const char*>(g_feats16) + lane * 4;
    const char* cwb = reinterpret_cast<const char*>(cw_s + wid * 960) + lane * 4;
    const uint2* mp = meta_s + wid * 32;

    float ox = 0.f, oy = 0.f;
    #pragma unroll 8
    for (int h = 0; h < 32; h++) {
        uint2 md = mp[h];
        uint32_t pk = md.x;
        float fl = __uint_as_float(md.y);
        __half2 fh = *reinterpret_cast<const __half2*>(fb + (pk & ~127u));
        __half2 wh = *reinterpret_cast<const __half2*>(cwb + ((pk & 127u) << 7));
        __half2 t  = __hmul2(fh, wh);
        float2 tf  = __half22float2(t);
        ox = fmaf(tf.x, fl, ox);
        oy = fmaf(tf.y, fl, oy);
    }
    *reinterpret_cast<float2*>(out + gm * 64 + 2 * lane) = make_float2(ox, oy);
}

// ================= launch =================
extern "C" void kernel_launch(void* const* d_in, const int* in_sizes, int n_in,
                              void* d_out, int out_size)
{
    const float* q_pts   = (const float*)d_in[0];
    const float* s_pts   = (const float*)d_in[1];
    const float* s_feats = (const float*)d_in[2];
    const int*   neighb  = (const int*)d_in[3];
    const float* kp      = (const float*)d_in[4];
    const float* W1      = (const float*)d_in[5];
    const float* gamma   = (const float*)d_in[6];
    const float* beta    = (const float*)d_in[7];
    const float* W2      = (const float*)d_in[8];
    const float* b2      = (const float*)d_in[9];
    float* out = (float*)d_out;

    const int N      = in_sizes[0] / 3;
    const int nb1    = (N + 127) / 128;
    const int nbMeta = (N * 32 + 255) / 256;

    cudaFuncSetAttribute(k1_feat_mm, cudaFuncAttributeMaxDynamicSharedMemorySize,
                         K1_SMEM_BYTES);
    cudaFuncSetAttribute(k4_gemm, cudaFuncAttributeMaxDynamicSharedMemorySize,
                         K4_SMEM);

    k1_feat_mm<<<nb1, 256, K1_SMEM_BYTES>>>(s_feats, W1, N);
    k2_bn_tr_meta<<<61 + nbMeta, 256>>>(gamma, beta, W2, q_pts, s_pts,
                                        neighb, kp, N, nb1);
    k3_act<<<(N * 32 + 255) / 256, 256>>>(N);
    dim3 g4(nb1, 15);
    k4_gemm<<<g4, 256, K4_SMEM>>>(b2, N);
    k5_agg<<<(N + 15) / 16, 512>>>(out, N);
}

// round 17
// speedup vs baseline: 1.2517x; 1.1216x over previous
#include <cuda_runtime.h>
#include <cuda_fp16.h>
#include <cstdint>

// ---------------- problem constants ----------------
#define SIGMA_INV (1.0f / 0.7f)
#define BN_EPS  1e-5f
#define MAXN    50176

// ---------------- scratch ----------------
__device__ float  g_h[MAXN * 64];            // pre-BN activations
__device__ float  g_part[512 * 128];         // BN partials
__device__ float  g_scale[64];
__device__ float  g_shift[64];
__device__ __half g_a16[MAXN * 64];          // fp16 post-activation
__device__ __half g_feats16[MAXN * 64];      // fp16 mirror of s_feats
__device__ __half g_w2t[960 * 64];           // W2^T fp16 [n][k]
__device__ __half g_cw[(size_t)MAXN * 960];  // conv weights fp16
__device__ uint2  g_meta[MAXN * 32];         // {id*128+k, infl bits}

// ---------------- f32x2 helpers ----------------
__device__ __forceinline__ unsigned long long pack2(float x, float y) {
    unsigned long long r;
    asm("mov.b64 %0, {%1, %2};" : "=l"(r) : "f"(x), "f"(y));
    return r;
}
__device__ __forceinline__ void unpack2(unsigned long long v, float& x, float& y) {
    asm("mov.b64 {%0, %1}, %2;" : "=f"(x), "=f"(y) : "l"(v));
}
__device__ __forceinline__ void fma2(unsigned long long& acc,
                                     unsigned long long a, unsigned long long b) {
    asm("fma.rn.f32x2 %0, %1, %2, %0;" : "+l"(acc) : "l"(a), "l"(b));
}
__device__ __forceinline__ void add2(unsigned long long& acc, unsigned long long a) {
    asm("add.rn.f32x2 %0, %0, %1;" : "+l"(acc) : "l"(a));
}

// ---------------- HMMA m16n8k16 + ldmatrix ----------------
__device__ __forceinline__ void mma16816(float* c, const uint32_t* a,
                                         uint32_t b0, uint32_t b1) {
    asm volatile(
        "mma.sync.aligned.m16n8k16.row.col.f32.f16.f16.f32 "
        "{%0,%1,%2,%3}, {%4,%5,%6,%7}, {%8,%9}, {%0,%1,%2,%3};"
        : "+f"(c[0]), "+f"(c[1]), "+f"(c[2]), "+f"(c[3])
        : "r"(a[0]), "r"(a[1]), "r"(a[2]), "r"(a[3]), "r"(b0), "r"(b1));
}
__device__ __forceinline__ void ldm_x4(uint32_t& r0, uint32_t& r1,
                                       uint32_t& r2, uint32_t& r3, uint32_t addr) {
    asm volatile("ldmatrix.sync.aligned.m8n8.x4.shared.b16 {%0,%1,%2,%3}, [%4];"
                 : "=r"(r0), "=r"(r1), "=r"(r2), "=r"(r3) : "r"(addr));
}

// ================= K1: h = s_feats @ W1 + BN partials + fp16 feats mirror =====
#define K1_SMEM_FLOATS (64 * 130 + 256)
#define K1_SMEM_BYTES  (K1_SMEM_FLOATS * 4)

__global__ void __launch_bounds__(256) k1_feat_mm(
    const float* __restrict__ s_feats, const float* __restrict__ W1, int N)
{
    extern __shared__ float sm1[];
    float* feat_t = sm1;
    float* red    = feat_t + 64 * 130;

    const int tid  = threadIdx.x;
    const int row0 = blockIdx.x * 128;

    #pragma unroll
    for (int it = 0; it < 8; it++) {
        int idx = it * 256 + tid;
        int r   = idx >> 4;
        int c0  = (idx & 15) * 4;
        float4 v = make_float4(0.f, 0.f, 0.f, 0.f);
        if (row0 + r < N) {
            v = *reinterpret_cast<const float4*>(s_feats + (row0 + r) * 64 + c0);
            __half2 h01 = __floats2half2_rn(v.x, v.y);
            __half2 h23 = __floats2half2_rn(v.z, v.w);
            uint2 hp;
            hp.x = *reinterpret_cast<uint32_t*>(&h01);
            hp.y = *reinterpret_cast<uint32_t*>(&h23);
            *reinterpret_cast<uint2*>(g_feats16 + (row0 + r) * 64 + c0) = hp;
        }
        feat_t[(c0 + 0) * 130 + r] = v.x;
        feat_t[(c0 + 1) * 130 + r] = v.y;
        feat_t[(c0 + 2) * 130 + r] = v.z;
        feat_t[(c0 + 3) * 130 + r] = v.w;
    }
    __syncthreads();

    const int cg = tid & 31, rg = tid >> 5;
    const int c0 = cg * 2;
    unsigned long long acc[2][8];
    #pragma unroll
    for (int cc = 0; cc < 2; cc++)
        #pragma unroll
        for (int p = 0; p < 8; p++) acc[cc][p] = 0ull;

    #pragma unroll 4
    for (int cp = 0; cp < 64; cp++) {
        unsigned long long wp = __ldg(
            reinterpret_cast<const unsigned long long*>(W1 + cp * 64 + c0));
        float w0, w1;
        unpack2(wp, w0, w1);
        unsigned long long w00 = pack2(w0, w0), w11 = pack2(w1, w1);
        const unsigned long long* ar =
            reinterpret_cast<const unsigned long long*>(feat_t + cp * 130 + rg * 16);
        #pragma unroll
        for (int p = 0; p < 8; p++) {
            unsigned long long a2 = ar[p];
            fma2(acc[0][p], a2, w00);
            fma2(acc[1][p], a2, w11);
        }
    }

    float sv[2], qv[2];
    #pragma unroll
    for (int cc = 0; cc < 2; cc++) {
        unsigned long long s2 = 0ull, q2 = 0ull;
        #pragma unroll
        for (int p = 0; p < 8; p++) {
            float x0, x1;
            unpack2(acc[cc][p], x0, x1);
            int r = row0 + rg * 16 + 2 * p;
            if (r < N)     g_h[r * 64 + c0 + cc] = x0;
            if (r + 1 < N) g_h[(r + 1) * 64 + c0 + cc] = x1;
            add2(s2, acc[cc][p]);
            fma2(q2, acc[cc][p], acc[cc][p]);
        }
        float ax, ay;
        unpack2(s2, ax, ay); sv[cc] = ax + ay;
        unpack2(q2, ax, ay); qv[cc] = ax + ay;
    }

    #pragma unroll
    for (int pass = 0; pass < 4; pass++) {
        float val = (pass < 2) ? sv[pass] : qv[pass - 2];
        __syncthreads();
        red[tid] = val;
        __syncthreads();
        if (tid < 32) {
            float t = 0.f;
            #pragma unroll
            for (int g = 0; g < 8; g++) t += red[g * 32 + tid];
            int c = tid * 2 + (pass & 1);
            g_part[blockIdx.x * 128 + ((pass < 2) ? 0 : 64) + c] = t;
        }
    }
}

// ====== K2: BN finalize (blk 0) + W2 transpose (blks 1..60) + meta (blks 61+) ==
__global__ void __launch_bounds__(256) k2_bn_tr_meta(
    const float* __restrict__ gamma, const float* __restrict__ beta,
    const float* __restrict__ W2,
    const float* __restrict__ q_pts, const float* __restrict__ s_pts,
    const int* __restrict__ neighb_inds, const float* __restrict__ kernel_points,
    int N, int nb)
{
    const int tid = threadIdx.x;

    if (blockIdx.x == 0) {
        __shared__ float red[256];
        const int c    = tid & 63;
        const int part = tid >> 6;
        float s = 0.f, q = 0.f;
        for (int b = part; b < nb; b += 4) {
            s += g_part[b * 128 + c];
            q += g_part[b * 128 + 64 + c];
        }
        red[tid] = s;
        __syncthreads();
        float sum = 0.f;
        if (tid < 64) sum = red[tid] + red[tid + 64] + red[tid + 128] + red[tid + 192];
        __syncthreads();
        red[tid] = q;
        __syncthreads();
        if (tid < 64) {
            float sq  = red[tid] + red[tid + 64] + red[tid + 128] + red[tid + 192];
            float inv = 1.f / (float)N;
            float mu  = sum * inv;
            float var = sq * inv - mu * mu;
            float sc  = gamma[tid] * rsqrtf(var + BN_EPS);
            g_scale[tid] = sc;
            g_shift[tid] = beta[tid] - mu * sc;
        }
        return;
    }

    if (blockIdx.x <= 60) {
        int o0 = (blockIdx.x - 1) * 1024 + tid * 4;
        #pragma unroll
        for (int e = 0; e < 4; e++) {
            int o = o0 + e;                 // < 61440
            int n = o >> 6, c = o & 63;
            g_w2t[o] = __float2half_rn(W2[c * 960 + n]);
        }
        return;
    }

    // ---------- metadata blocks ----------
    int i = (blockIdx.x - 61) * 256 + tid;
    if (i >= N * 32) return;
    int m = i >> 5;
    int id = neighb_inds[i];
    uint32_t packed = 0u;
    float infl = 0.f;
    if ((unsigned)id < (unsigned)N) {
        float qx = __ldg(q_pts + m * 3 + 0);
        float qy = __ldg(q_pts + m * 3 + 1);
        float qz = __ldg(q_pts + m * 3 + 2);
        float nx = __ldg(s_pts + id * 3 + 0) - qx;
        float ny = __ldg(s_pts + id * 3 + 1) - qy;
        float nz = __ldg(s_pts + id * 3 + 2) - qz;
        float best = 1e30f;
        int kb = 0;
        #pragma unroll
        for (int k = 0; k < 15; k++) {
            float dx = nx - __ldg(kernel_points + k * 3 + 0);
            float dy = ny - __ldg(kernel_points + k * 3 + 1);
            float dz = nz - __ldg(kernel_points + k * 3 + 2);
            float d = fmaf(dx, dx, fmaf(dy, dy, dz * dz));
            if (d < best) { best = d; kb = k; }
        }
        infl = fmaxf(0.f, 1.f - sqrtf(best) * SIGMA_INV);
        packed = (uint32_t)id * 128u + (uint32_t)kb;
    }
    g_meta[i] = make_uint2(packed, __float_as_uint(infl));
}

// ================= K3: activation -> fp16 (once) ==============================
__global__ void __launch_bounds__(256) k3_act(int N)
{
    int p = blockIdx.x * 256 + threadIdx.x;
    if (p >= N * 32) return;
    int c = (p & 31) * 2;
    float2 h  = *reinterpret_cast<const float2*>(g_h + 2 * p);
    float2 sc = *reinterpret_cast<const float2*>(g_scale + c);
    float2 sh = *reinterpret_cast<const float2*>(g_shift + c);
    float x = fmaf(h.x, sc.x, sh.x); x = (x > 0.f) ? x : 0.1f * x;
    float y = fmaf(h.y, sc.y, sh.y); y = (y > 0.f) ? y : 0.1f * y;
    *reinterpret_cast<__half2*>(g_a16 + 2 * p) = __floats2half2_rn(x, y);
}

// ===== K4: (128-row m-tile) x (64-col n-chunk) grid; ldmatrix + staged stores =
// smem: A_s 128x72 (18432) + B_s 64x72 (9216) = 27648 B; O aliases A_s.
#define AS 72
#define K4_SMEM (18432 + 9216)

__global__ void __launch_bounds__(256) k4_gemm(const float* __restrict__ b2, int N)
{
    extern __shared__ char sm4[];
    __half* A_s = (__half*)sm4;
    __half* B_s = (__half*)(sm4 + 18432);

    const int tid  = threadIdx.x;
    const int lane = tid & 31, w = tid >> 5;
    const int wm = w & 1, wn = w >> 1;
    const int row0 = blockIdx.x * 128;
    const int n0   = blockIdx.y * 64;

    // load A tile: 128 rows x 128B fp16 (8 uint4 per row)
    #pragma unroll
    for (int it = 0; it < 4; it++) {
        int idx = it * 256 + tid;
        int r = idx >> 3, c8 = idx & 7;
        uint4 v = make_uint4(0u, 0u, 0u, 0u);
        if (row0 + r < N)
            v = *reinterpret_cast<const uint4*>(g_a16 + (row0 + r) * 64 + c8 * 8);
        *reinterpret_cast<uint4*>(A_s + r * AS + c8 * 8) = v;
    }
    // load B tile: 64 rows x 128B
    #pragma unroll
    for (int it = 0; it < 2; it++) {
        int idx = it * 256 + tid;
        int r = idx >> 3, c8 = idx & 7;
        *reinterpret_cast<uint4*>(B_s + r * AS + c8 * 8) =
            *reinterpret_cast<const uint4*>(g_w2t + (n0 + r) * 64 + c8 * 8);
    }
    __syncthreads();

    // ldmatrix lane address components
    const int lr  = lane & 7;
    const int g1  = (lane >> 3) & 1;
    const int g2  = lane >> 4;

    uint32_t a_base[4];
    #pragma unroll
    for (int i = 0; i < 4; i++) {
        int rowA = wm * 64 + i * 16 + g1 * 8 + lr;
        a_base[i] = (uint32_t)__cvta_generic_to_shared(A_s + rowA * AS + g2 * 8);
    }
    int rowB = wn * 16 + g2 * 8 + lr;
    uint32_t b_base = (uint32_t)__cvta_generic_to_shared(B_s + rowB * AS + g1 * 8);

    float acc[4][2][4];
    #pragma unroll
    for (int i = 0; i < 4; i++)
        #pragma unroll
        for (int j = 0; j < 2; j++)
            #pragma unroll
            for (int q = 0; q < 4; q++) acc[i][j][q] = 0.f;

    #pragma unroll
    for (int ks = 0; ks < 4; ks++) {
        const uint32_t koff = ks * 32;     // 16 halfs = 32 bytes
        uint32_t b0j0, b1j0, b0j1, b1j1;
        ldm_x4(b0j0, b1j0, b0j1, b1j1, b_base + koff);
        #pragma unroll
        for (int i = 0; i < 4; i++) {
            uint32_t a[4];
            ldm_x4(a[0], a[1], a[2], a[3], a_base[i] + koff);
            mma16816(acc[i][0], a, b0j0, b1j0);
            mma16816(acc[i][1], a, b0j1, b1j1);
        }
    }

    // ---- epilogue: bias + fp16 into O_s (aliases A_s, stride 72 -> no bank
    //      conflicts: rows 144B apart => bank r*4 mod 32, lanes all distinct) ----
    __syncthreads();                        // A_s fragment reads complete
    __half* O_s = A_s;
    const int mrow = lane >> 2;
    const int kcol = (lane & 3) * 2;
    #pragma unroll
    for (int j = 0; j < 2; j++) {
        int colL = wn * 16 + j * 8 + kcol;  // 0..63
        float bx = __ldg(b2 + n0 + colL);
        float by = __ldg(b2 + n0 + colL + 1);
        #pragma unroll
        for (int i = 0; i < 4; i++) {
            int rL = wm * 64 + i * 16 + mrow;
            *reinterpret_cast<__half2*>(O_s + rL * AS + colL) =
                __floats2half2_rn(acc[i][j][0] + bx, acc[i][j][1] + by);
            *reinterpret_cast<__half2*>(O_s + (rL + 8) * AS + colL) =
                __floats2half2_rn(acc[i][j][2] + bx, acc[i][j][3] + by);
        }
    }
    __syncthreads();

    // coalesced store: 128 rows x 128B (8 uint4/row, full sectors)
    #pragma unroll
    for (int it = 0; it < 4; it++) {
        int idx = it * 256 + tid;            // 0..1023
        int r = idx >> 3, c = (idx & 7) * 8;
        if (row0 + r < N)
            *reinterpret_cast<uint4*>(g_cw + (size_t)(row0 + r) * 960 + n0 + c) =
                *reinterpret_cast<const uint4*>(O_s + r * AS + c);
    }
}

// ================= K5: aggregation (proven R11 version) =======================
__global__ void __launch_bounds__(512) k5_agg(float* __restrict__ out, int N)
{
    __shared__ __half cw_s[16 * 960];
    __shared__ uint2  meta_s[512];

    const int tid = threadIdx.x;
    const int m0  = blockIdx.x * 16;

    {
        const uint4* src = reinterpret_cast<const uint4*>(g_cw + (size_t)m0 * 960);
        uint4* dst = reinterpret_cast<uint4*>(cw_s);
        #pragma unroll
        for (int it = 0; it < 4; it++) {
            int i = it * 512 + tid;
            if (i < 1920 && (m0 + i / 120) < N) dst[i] = src[i];
        }
    }
    {
        int i = m0 * 32 + tid;
        if (i < N * 32) meta_s[tid] = g_meta[i];
    }
    __syncthreads();

    const int wid = tid >> 5, lane = tid & 31;
    const int gm = m0 + wid;
    if (gm >= N) return;

    const char* fb  = reinterpret_cast<const char*>(g_feats16) + lane * 4;
    const char* cwb = reinterpret_cast<const char*>(cw_s + wid * 960) + lane * 4;
    const uint2* mp = meta_s + wid * 32;

    float ox = 0.f, oy = 0.f;
    #pragma unroll 8
    for (int h = 0; h < 32; h++) {
        uint2 md = mp[h];
        uint32_t pk = md.x;
        float fl = __uint_as_float(md.y);
        __half2 fh = *reinterpret_cast<const __half2*>(fb + (pk & ~127u));
        __half2 wh = *reinterpret_cast<const __half2*>(cwb + ((pk & 127u) << 7));
        __half2 t  = __hmul2(fh, wh);
        float2 tf  = __half22float2(t);
        ox = fmaf(tf.x, fl, ox);
        oy = fmaf(tf.y, fl, oy);
    }
    *reinterpret_cast<float2*>(out + gm * 64 + 2 * lane) = make_float2(ox, oy);
}

// ================= launch =================
extern "C" void kernel_launch(void* const* d_in, const int* in_sizes, int n_in,
                              void* d_out, int out_size)
{
    const float* q_pts   = (const float*)d_in[0];
    const float* s_pts   = (const float*)d_in[1];
    const float* s_feats = (const float*)d_in[2];
    const int*   neighb  = (const int*)d_in[3];
    const float* kp      = (const float*)d_in[4];
    const float* W1      = (const float*)d_in[5];
    const float* gamma   = (const float*)d_in[6];
    const float* beta    = (const float*)d_in[7];
    const float* W2      = (const float*)d_in[8];
    const float* b2      = (const float*)d_in[9];
    float* out = (float*)d_out;

    const int N      = in_sizes[0] / 3;
    const int nb1    = (N + 127) / 128;
    const int nbMeta = (N * 32 + 255) / 256;

    cudaFuncSetAttribute(k1_feat_mm, cudaFuncAttributeMaxDynamicSharedMemorySize,
                         K1_SMEM_BYTES);
    cudaFuncSetAttribute(k4_gemm, cudaFuncAttributeMaxDynamicSharedMemorySize,
                         K4_SMEM);

    k1_feat_mm<<<nb1, 256, K1_SMEM_BYTES>>>(s_feats, W1, N);
    k2_bn_tr_meta<<<61 + nbMeta, 256>>>(gamma, beta, W2, q_pts, s_pts,
                                        neighb, kp, N, nb1);
    k3_act<<<(N * 32 + 255) / 256, 256>>>(N);
    dim3 g4(nb1, 15);
    k4_gemm<<<g4, 256, K4_SMEM>>>(b2, N);
    k5_agg<<<(N + 15) / 16, 512>>>(out, N);
}